// round 2
// baseline (speedup 1.0000x reference)
#include <cuda_runtime.h>
#include <cstdint>

// RochetNet forward, two-phase:
//   Phase A: fast packed-f32x2 scoring; rows whose top-2 gap is large are
//            finalized directly (argmax is rounding-order invariant there).
//   Phase B: near-tie rows are rescored with a strict serial-order fp32 FMA
//            chain (i = 0..63, then + w0 as one add) to bit-match the
//            reference's accumulation order, fixing argmax on ties.
//
// Output layout: alloc [B*64] floats, then payments [B].

#define ITEMS   64
#define HIDDEN  256
#define TPB     256
#define BMAX    1000000
#define GAP_THR 2e-3f

__device__ int g_tie_count;
__device__ int g_tie_rows[BMAX];

__device__ __forceinline__ unsigned long long fma2(unsigned long long a,
                                                   unsigned long long b,
                                                   unsigned long long c) {
    unsigned long long d;
    asm("fma.rn.f32x2 %0, %1, %2, %3;" : "=l"(d) : "l"(a), "l"(b), "l"(c));
    return d;
}

__global__ void zero_count_kernel() { g_tie_count = 0; }

// ---------------------------------------------------------------- Phase A ---
__global__ __launch_bounds__(TPB, 2)
void rochet_phaseA_kernel(const float* __restrict__ V,
                          const float* __restrict__ W,
                          const float* __restrict__ w0,
                          float* __restrict__ alloc_out,
                          float* __restrict__ pay_out,
                          int B) {
    extern __shared__ float sh[];
    float* Wsh  = sh;                      // HIDDEN*ITEMS floats (64 KB)
    float* w0sh = sh + HIDDEN * ITEMS;     // HIDDEN floats

    const int tid = threadIdx.x;
    {
        const float4* Wg4 = reinterpret_cast<const float4*>(W);
        float4*       Ws4 = reinterpret_cast<float4*>(Wsh);
        #pragma unroll
        for (int i = tid; i < HIDDEN * ITEMS / 4; i += TPB) Ws4[i] = Wg4[i];
        for (int i = tid; i < HIDDEN; i += TPB) w0sh[i] = w0[i];
    }
    __syncthreads();

    const long long row = (long long)blockIdx.x * TPB + tid;
    if (row >= B) return;

    unsigned long long v2[ITEMS / 2];
    {
        const ulonglong2* vg =
            reinterpret_cast<const ulonglong2*>(V + (size_t)row * ITEMS);
        #pragma unroll
        for (int i = 0; i < ITEMS / 4; i++) {
            ulonglong2 t = vg[i];
            v2[2 * i + 0] = t.x;
            v2[2 * i + 1] = t.y;
        }
    }

    float best = -1e30f, second = -1e30f;
    int   bidx = 0;
    #pragma unroll 1
    for (int j = 0; j < HIDDEN; j++) {
        const ulonglong2* wr =
            reinterpret_cast<const ulonglong2*>(Wsh + j * ITEMS);
        unsigned long long a0 = 0ull, a1 = 0ull;
        #pragma unroll
        for (int i = 0; i < ITEMS / 4; i++) {
            ulonglong2 t = wr[i];             // broadcast LDS.128
            a0 = fma2(v2[2 * i + 0], t.x, a0);
            a1 = fma2(v2[2 * i + 1], t.y, a1);
        }
        float2 f0 = *reinterpret_cast<float2*>(&a0);
        float2 f1 = *reinterpret_cast<float2*>(&a1);
        float h = ((f0.x + f0.y) + (f1.x + f1.y)) + w0sh[j];
        if (h > best) { second = best; best = h; bidx = j; }
        else if (h > second) { second = h; }
    }

    if (best - second <= GAP_THR) {
        // Near tie: defer to exact-order rescoring in Phase B.
        int slot = atomicAdd(&g_tie_count, 1);
        g_tie_rows[slot] = (int)row;
        return;
    }

    const bool win = (best > 0.0f);
    float4* out4 = reinterpret_cast<float4*>(alloc_out + (size_t)row * ITEMS);
    const float4* wrow4 = reinterpret_cast<const float4*>(Wsh + bidx * ITEMS);
    float pd = 0.0f;
    #pragma unroll
    for (int i = 0; i < ITEMS / 4; i++) {
        float4 t = wrow4[i];
        t.x = fminf(fmaxf(t.x, 0.0f), 1.0f);
        t.y = fminf(fmaxf(t.y, 0.0f), 1.0f);
        t.z = fminf(fmaxf(t.z, 0.0f), 1.0f);
        t.w = fminf(fmaxf(t.w, 0.0f), 1.0f);
        if (!win) { t.x = 0.0f; t.y = 0.0f; t.z = 0.0f; t.w = 0.0f; }
        float2 va = *reinterpret_cast<float2*>(&v2[2 * i + 0]);
        float2 vb = *reinterpret_cast<float2*>(&v2[2 * i + 1]);
        pd = fmaf(t.x, va.x, pd);
        pd = fmaf(t.y, va.y, pd);
        pd = fmaf(t.z, vb.x, pd);
        pd = fmaf(t.w, vb.y, pd);
        out4[i] = t;
    }
    pay_out[row] = fmaxf(pd - fmaxf(best, 0.0f), 0.0f);
}

// ---------------------------------------------------------------- Phase B ---
// One warp per queued row. Each lane scores 8 hidden units with a strict
// serial-order fp32 FMA chain (matches reference accumulation order).
__global__ __launch_bounds__(256)
void rochet_phaseB_kernel(const float* __restrict__ V,
                          const float* __restrict__ W,
                          const float* __restrict__ w0,
                          float* __restrict__ alloc_out,
                          float* __restrict__ pay_out) {
    const int lane        = threadIdx.x & 31;
    const int warp_global = (blockIdx.x * blockDim.x + threadIdx.x) >> 5;
    const int nwarps      = (gridDim.x * blockDim.x) >> 5;
    const int cnt         = g_tie_count;

    for (int q = warp_global; q < cnt; q += nwarps) {
        const int row = g_tie_rows[q];
        const float* v = V + (size_t)row * ITEMS;

        float vr[ITEMS];
        #pragma unroll
        for (int i = 0; i < ITEMS / 4; i++) {
            float4 t = reinterpret_cast<const float4*>(v)[i];
            vr[4 * i + 0] = t.x; vr[4 * i + 1] = t.y;
            vr[4 * i + 2] = t.z; vr[4 * i + 3] = t.w;
        }

        float best = -1e30f;
        int   bidx = HIDDEN;
        #pragma unroll 1
        for (int jj = 0; jj < HIDDEN / 32; jj++) {
            const int j = lane * (HIDDEN / 32) + jj;   // ascending within lane
            const float* wr = W + j * ITEMS;
            float acc = 0.0f;
            #pragma unroll
            for (int i = 0; i < ITEMS; i++)
                acc = fmaf(vr[i], __ldg(wr + i), acc); // strict serial order
            float h = acc + __ldg(w0 + j);             // single bias rounding
            if (h > best || (h == best && j < bidx)) { best = h; bidx = j; }
        }
        // Warp argmax reduce, first-index tie-break.
        #pragma unroll
        for (int off = 16; off; off >>= 1) {
            float ov = __shfl_down_sync(0xffffffffu, best, off);
            int   oi = __shfl_down_sync(0xffffffffu, bidx, off);
            if (ov > best || (ov == best && oi < bidx)) { best = ov; bidx = oi; }
        }
        best = __shfl_sync(0xffffffffu, best, 0);
        bidx = __shfl_sync(0xffffffffu, bidx, 0);

        const bool win = (best > 0.0f);
        float w_0 = __ldg(W + bidx * ITEMS + 2 * lane + 0);
        float w_1 = __ldg(W + bidx * ITEMS + 2 * lane + 1);
        w_0 = fminf(fmaxf(w_0, 0.0f), 1.0f);
        w_1 = fminf(fmaxf(w_1, 0.0f), 1.0f);
        if (!win) { w_0 = 0.0f; w_1 = 0.0f; }
        alloc_out[(size_t)row * ITEMS + 2 * lane + 0] = w_0;
        alloc_out[(size_t)row * ITEMS + 2 * lane + 1] = w_1;

        float pd = fmaf(w_1, vr[2 * lane + 1], w_0 * vr[2 * lane]);
        #pragma unroll
        for (int off = 16; off; off >>= 1)
            pd += __shfl_down_sync(0xffffffffu, pd, off);
        if (lane == 0)
            pay_out[row] = fmaxf(pd - fmaxf(best, 0.0f), 0.0f);
    }
}

extern "C" void kernel_launch(void* const* d_in, const int* in_sizes, int n_in,
                              void* d_out, int out_size) {
    const float* V  = (const float*)d_in[0];   // [B, 64]
    const float* W  = (const float*)d_in[1];   // [256, 64]
    const float* w0 = (const float*)d_in[2];   // [256]

    const int B = in_sizes[0] / ITEMS;
    float* alloc_out = (float*)d_out;
    float* pay_out   = (float*)d_out + (size_t)B * ITEMS;

    const size_t shbytes = (size_t)(HIDDEN * ITEMS + HIDDEN) * sizeof(float);
    cudaFuncSetAttribute(rochet_phaseA_kernel,
                         cudaFuncAttributeMaxDynamicSharedMemorySize,
                         (int)shbytes);

    zero_count_kernel<<<1, 1>>>();
    rochet_phaseA_kernel<<<(B + TPB - 1) / TPB, TPB, shbytes>>>(
        V, W, w0, alloc_out, pay_out, B);
    rochet_phaseB_kernel<<<512, 256>>>(V, W, w0, alloc_out, pay_out);
}